// round 14
// baseline (speedup 1.0000x reference)
#include <cuda_runtime.h>
#include <cstdint>

#define BB 64
#define PP 32768
#define OO 50

#define MT 256   // k_match threads per block
#define MR 4     // priors per thread in k_match

// ---------------- scratch (device globals; no allocations allowed) ----------------
__device__ unsigned long long g_bestprior[BB * OO];  // (ratio_bits<<32)|~prior
__device__ unsigned short g_conf[(size_t)BB * PP];   // conf_t (low 8) | tidx << 8
__device__ unsigned int g_keys[(size_t)BB * PP];     // lc bits for mining (pos -> 0)
__device__ int g_numpos[BB];
__device__ float g_accum[4];  // 0: loss_l, 1: pos lc sum, 2: mined neg lc sum
__device__ int g_N;

// ---------------- helpers ----------------
__device__ __forceinline__ float blockReduceSumF(float v, float* sbuf) {
    __syncthreads();
    #pragma unroll
    for (int o = 16; o > 0; o >>= 1) v += __shfl_down_sync(0xffffffffu, v, o);
    int lane = threadIdx.x & 31, w = threadIdx.x >> 5;
    if (lane == 0) sbuf[w] = v;
    __syncthreads();
    int nw = blockDim.x >> 5;
    v = (threadIdx.x < nw) ? sbuf[threadIdx.x] : 0.f;
    if (w == 0) {
        #pragma unroll
        for (int o = 16; o > 0; o >>= 1) v += __shfl_down_sync(0xffffffffu, v, o);
    }
    return v;  // valid on tid 0
}

__device__ __forceinline__ int blockReduceSumI(int v, int* sbuf) {
    __syncthreads();
    #pragma unroll
    for (int o = 16; o > 0; o >>= 1) v += __shfl_down_sync(0xffffffffu, v, o);
    int lane = threadIdx.x & 31, w = threadIdx.x >> 5;
    if (lane == 0) sbuf[w] = v;
    __syncthreads();
    int nw = blockDim.x >> 5;
    v = (threadIdx.x < nw) ? sbuf[threadIdx.x] : 0;
    if (w == 0) {
        #pragma unroll
        for (int o = 16; o > 0; o >>= 1) v += __shfl_down_sync(0xffffffffu, v, o);
    }
    return v;
}

// ---------------- kernel 0: init ----------------
__global__ void k_init() {
    int i = blockIdx.x * blockDim.x + threadIdx.x;
    if (i < BB * OO) g_bestprior[i] = 0xFFFFFFFFull;  // ratio=0, prior=0 (stored ~p)
    if (i < BB) g_numpos[i] = 0;
    if (i < 4) g_accum[i] = 0.f;
    if (i == 4) g_N = 0;
}

// ---------------- kernel 1: IOU matching (u-key + IMNMX argmax) ----------------
// iou = inter/(S-inter) = g(inter/S), g strictly increasing => ordering by
// u = inter/S equals ordering by iou. Key = (u_bits & ~63) | (63-t):
// u >= 0 so bits are unsigned-monotone; among equal truncated u the larger
// tcode (= smaller t) wins => first-occurrence tie-break like jnp.argmax.
// Argmax over 50 truths = one unsigned max per pair (no predicates, lat 4).
// Per-truth best prior: u-space shared gate with conservative margin; rare
// path computes the exact ratio and atomicMax's the authoritative global.
__global__ void __launch_bounds__(MT) k_match(const float4* __restrict__ priors4,
                                              const float* __restrict__ targets) {
    const int b = blockIdx.y;
    __shared__ float4 s_t[OO];
    __shared__ float s_a[OO];
    __shared__ unsigned int s_gate[OO];    // max u bits seen (block-local filter)
    __shared__ unsigned char s_lab[OO];
    const int tid = threadIdx.x;
    if (tid < OO) {
        const float* tp = targets + ((size_t)b * OO + tid) * 5;
        float4 t;
        t.x = tp[0]; t.y = tp[1]; t.z = tp[2]; t.w = tp[3];
        s_t[tid] = t;
        s_a[tid] = (t.z - t.x) * (t.w - t.y);
        s_gate[tid] = 0u;
        s_lab[tid] = (tp[4] >= 0.f) ? 1 : 0;
    }
    __syncthreads();

    const int pbase = blockIdx.x * (MT * MR) + tid;
    float px1[MR], py1[MR], px2[MR], py2[MR], ab[MR];
    unsigned int best[MR];
    #pragma unroll
    for (int r = 0; r < MR; r++) {
        const float4 pr = priors4[pbase + r * MT];
        px1[r] = pr.x - pr.z * 0.5f; py1[r] = pr.y - pr.w * 0.5f;
        px2[r] = pr.x + pr.z * 0.5f; py2[r] = pr.y + pr.w * 0.5f;
        ab[r] = (px2[r] - px1[r]) * (py2[r] - py1[r]);
        best[r] = 0u;
    }

    #pragma unroll 2
    for (int t = 0; t < OO; t++) {
        const float4 tb = s_t[t];
        const float at = s_a[t];
        float gthr = __uint_as_float(s_gate[t]) * 0.99999f;  // margin: near-ties fall through
        const unsigned int tcode = 63u - (unsigned int)t;
        #pragma unroll
        for (int r = 0; r < MR; r++) {
            const float w = fminf(tb.z, px2[r]) - fmaxf(tb.x, px1[r]);
            const float h = fminf(tb.w, py2[r]) - fmaxf(tb.y, py1[r]);
            const float inter = fmaxf(w, 0.f) * fmaxf(h, 0.f);
            const float S = at + ab[r];
            const float u = __fdividef(inter, S);            // MUFU pipe
            const unsigned int key = (__float_as_uint(u) & 0xFFFFFFC0u) | tcode;
            best[r] = (key > best[r]) ? key : best[r];       // IMNMX.U32
            if (u > gthr) {  // rare path: exact ratio is authoritative
                const unsigned int ub = __float_as_uint(u);
                const unsigned int old = atomicMax(&s_gate[t], ub);
                const float ratio = inter / (S - inter);
                const unsigned long long pk =
                    ((unsigned long long)__float_as_uint(ratio) << 32) |
                    (unsigned int)(~(pbase + r * MT));
                atomicMax(&g_bestprior[b * OO + t], pk);
                const unsigned int ng = ub > old ? ub : old;
                gthr = __uint_as_float(ng) * 0.99999f;
            }
        }
    }

    #pragma unroll
    for (int r = 0; r < MR; r++) {
        const int t = 63 - (int)(best[r] & 63u);
        const float u_best = __uint_as_float(best[r] & 0xFFFFFFC0u);
        // iou >= 0.5  <=>  u >= 1/3
        const int conf = (u_best >= (1.0f / 3.0f)) ? (int)s_lab[t] : 0;
        g_conf[(size_t)b * PP + pbase + r * MT] =
            (unsigned short)(conf | (t << 8));
    }
}

// ---------------- kernel 2: per-truth best-prior override ----------------
// Per batch b, ascending t by a single lane preserves last-write-wins on
// duplicate winning priors (matches jax .at[].set semantics).
__global__ void k_override(const float* __restrict__ targets) {
    const int b = blockIdx.x * blockDim.x + threadIdx.x;
    if (b >= BB) return;
    for (int t = 0; t < OO; t++) {
        const unsigned long long pk = g_bestprior[b * OO + t];
        const unsigned int p = ~(unsigned int)(pk & 0xFFFFFFFFu);
        const int lab = (targets[((size_t)b * OO + t) * 5 + 4] >= 0.f) ? 1 : 0;
        g_conf[(size_t)b * PP + p] = (unsigned short)(lab | (t << 8));  // ovl := 2 => pos
    }
}

// ---------------- kernel 3: per-prior loss terms (4 priors/thread) ----------------
__global__ void __launch_bounds__(256) k_loss(const float4* __restrict__ arm_loc4,
                                              const float4* __restrict__ arm_conf4,
                                              const float4* __restrict__ priors4,
                                              const float* __restrict__ targets) {
    __shared__ float sbufF[32];
    __shared__ int sbufI[32];
    const int b = blockIdx.y;
    const int tid = threadIdx.x;
    const int p0 = (blockIdx.x * 256 + tid) * 4;      // 4 consecutive priors
    const size_t off0 = (size_t)b * PP + p0;

    const ushort4 ct4 = *reinterpret_cast<const ushort4*>(&g_conf[off0]);
    const float4 ca = arm_conf4[off0 >> 1];
    const float4 cb = arm_conf4[(off0 >> 1) + 1];

    unsigned short cts[4] = {ct4.x, ct4.y, ct4.z, ct4.w};
    float c0s[4] = {ca.x, ca.z, cb.x, cb.z};
    float c1s[4] = {ca.y, ca.w, cb.y, cb.w};

    float ll = 0.f, plc = 0.f;
    int np = 0;
    uint4 keys;
    unsigned int* kp = reinterpret_cast<unsigned int*>(&keys);

    #pragma unroll
    for (int j = 0; j < 4; j++) {
        const int conf = cts[j] & 0xFF;
        const int t = cts[j] >> 8;
        const bool pos = conf > 0;
        const float z = pos ? (c0s[j] - c1s[j]) : (c1s[j] - c0s[j]);
        const float lc = fmaxf(z, 0.f) + __logf(1.0f + __expf(-fabsf(z)));
        kp[j] = pos ? 0u : __float_as_uint(lc);
        if (pos) {
            np++; plc += lc;
            const float* tb = targets + ((size_t)b * OO + t) * 5;
            const float x1 = tb[0], y1 = tb[1], x2 = tb[2], y2 = tb[3];
            const float4 pr = priors4[p0 + j];
            const float gcx = ((x1 + x2) * 0.5f - pr.x) / (0.1f * pr.z);
            const float gcy = ((y1 + y2) * 0.5f - pr.y) / (0.1f * pr.w);
            const float gw = logf((x2 - x1) / pr.z) / 0.2f;
            const float gh = logf((y2 - y1) / pr.w) / 0.2f;
            const float4 al = arm_loc4[off0 + j];
            const float d0 = al.x - gcx, d1 = al.y - gcy, d2 = al.z - gw, d3 = al.w - gh;
            #define SL1(d) (fabsf(d) < 1.f ? 0.5f * (d) * (d) : fabsf(d) - 0.5f)
            ll += SL1(d0) + SL1(d1) + SL1(d2) + SL1(d3);
            #undef SL1
        }
    }
    *reinterpret_cast<uint4*>(&g_keys[off0]) = keys;

    const float llT = blockReduceSumF(ll, sbufF);
    const float plcT = blockReduceSumF(plc, sbufF);
    const int cntT = blockReduceSumI(np, sbufI);
    if (tid == 0) {
        if (llT != 0.f) atomicAdd(&g_accum[0], llT);
        if (plcT != 0.f) atomicAdd(&g_accum[1], plcT);
        if (cntT != 0) { atomicAdd(&g_numpos[b], cntT); atomicAdd(&g_N, cntT); }
    }
}

// ---------------- kernel 4: per-batch top-K sum via radix select (parallel scan) ----------------
__global__ void k_select() {
    extern __shared__ unsigned int s_keys[];  // PP uint32 = 128KB
    __shared__ int hist[256];
    __shared__ int ssum[256];   // inclusive suffix sums, indexed by tid (= 255 - digit)
    __shared__ int s_wsum[8];
    __shared__ int s_sel, s_rem;
    __shared__ float sbufF[32];
    __shared__ int sbufI[32];
    const int b = blockIdx.x;
    const int tid = threadIdx.x;  // 1024

    const int np = g_numpos[b];
    int K = 3 * np;
    if (K > PP - 1) K = PP - 1;
    if (K <= 0) return;  // uniform across block

    for (int i = tid; i < PP / 4; i += 1024)
        reinterpret_cast<uint4*>(s_keys)[i] =
            reinterpret_cast<const uint4*>(&g_keys[(size_t)b * PP])[i];
    __syncthreads();

    unsigned int prefix = 0, mask = 0;
    int remaining = K;
    for (int pass = 0; pass < 4; pass++) {
        const int shift = 24 - 8 * pass;
        if (tid < 256) hist[tid] = 0;
        __syncthreads();
        for (int i = tid; i < PP; i += 1024) {
            const unsigned int k = s_keys[i];
            if ((k & mask) == prefix) atomicAdd(&hist[(k >> shift) & 0xFFu], 1);
        }
        __syncthreads();

        // parallel suffix scan over 256 bins (tid -> digit 255-tid)
        int x = 0;
        if (tid < 256) {
            x = hist[255 - tid];
            #pragma unroll
            for (int o = 1; o < 32; o <<= 1) {
                const int y = __shfl_up_sync(0xffffffffu, x, o);
                if ((tid & 31) >= o) x += y;
            }
            if ((tid & 31) == 31) s_wsum[tid >> 5] = x;
        }
        __syncthreads();
        if (tid == 0) {
            int acc = 0;
            #pragma unroll
            for (int i = 0; i < 8; i++) { const int v = s_wsum[i]; s_wsum[i] = acc; acc += v; }
        }
        __syncthreads();
        int incl = 0;
        if (tid < 256) {
            incl = x + s_wsum[tid >> 5];
            ssum[tid] = incl;
        }
        __syncthreads();
        if (tid < 256) {
            const int above = tid ? ssum[tid - 1] : 0;  // count strictly above this digit
            if (incl >= remaining && above < remaining) {
                s_sel = 255 - tid;
                s_rem = remaining - above;
            }
        }
        __syncthreads();
        prefix |= ((unsigned int)s_sel) << shift;
        mask |= 0xFFu << shift;
        remaining = s_rem;
        __syncthreads();
    }

    const float kth = __uint_as_float(prefix);
    float sum = 0.f;
    int cnt = 0;
    for (int i = tid; i < PP; i += 1024) {
        const unsigned int k = s_keys[i];
        if (k > prefix) { sum += __uint_as_float(k); cnt++; }
    }
    const float sumT = blockReduceSumF(sum, sbufF);
    const int cntT = blockReduceSumI(cnt, sbufI);
    if (tid == 0) {
        const float total = sumT + (float)(K - cntT) * kth;
        atomicAdd(&g_accum[2], total);
    }
}

// ---------------- kernel 5: final combine ----------------
__global__ void k_final(float* __restrict__ out) {
    if (threadIdx.x == 0) {
        const float fN = (float)g_N;
        out[0] = g_accum[0] / fN;
        out[1] = (g_accum[1] + g_accum[2]) / fN;
    }
}

// ---------------- launch ----------------
extern "C" void kernel_launch(void* const* d_in, const int* in_sizes, int n_in,
                              void* d_out, int out_size) {
    const float* arm_loc  = (const float*)d_in[0];
    const float* arm_conf = (const float*)d_in[1];
    // d_in[2], d_in[3]: odm_loc / odm_conf unused by the reference loss
    const float* priors   = (const float*)d_in[4];
    const float* targets  = (const float*)d_in[5];
    float* out = (float*)d_out;

    cudaFuncSetAttribute(k_select, cudaFuncAttributeMaxDynamicSharedMemorySize, PP * 4);

    k_init<<<(BB * OO + 255) / 256, 256>>>();
    dim3 g1(PP / (MT * MR), BB);
    k_match<<<g1, MT>>>(reinterpret_cast<const float4*>(priors), targets);
    k_override<<<1, BB>>>(targets);
    dim3 g3(PP / (256 * 4), BB);
    k_loss<<<g3, 256>>>(reinterpret_cast<const float4*>(arm_loc),
                        reinterpret_cast<const float4*>(arm_conf),
                        reinterpret_cast<const float4*>(priors), targets);
    k_select<<<BB, 1024, PP * 4>>>();
    k_final<<<1, 32>>>(out);
}

// round 15
// speedup vs baseline: 2.0146x; 2.0146x over previous
#include <cuda_runtime.h>
#include <cstdint>

#define BB 64
#define PP 32768
#define OO 50

#define MT 256   // k_match threads per block
#define MR 4     // priors per thread in k_match

// ---------------- scratch (device globals; no allocations allowed) ----------------
__device__ unsigned long long g_bestprior[BB * OO];  // (ratio_bits<<32)|~prior
__device__ unsigned short g_conf[(size_t)BB * PP];   // conf_t (low 8) | tidx << 8
__device__ unsigned int g_keys[(size_t)BB * PP];     // lc bits for mining (pos -> 0)
__device__ int g_numpos[BB];
__device__ float g_accum[4];  // 0: loss_l, 1: pos lc sum, 2: mined neg lc sum
__device__ int g_N;

// ---------------- helpers ----------------
__device__ __forceinline__ float blockReduceSumF(float v, float* sbuf) {
    __syncthreads();
    #pragma unroll
    for (int o = 16; o > 0; o >>= 1) v += __shfl_down_sync(0xffffffffu, v, o);
    int lane = threadIdx.x & 31, w = threadIdx.x >> 5;
    if (lane == 0) sbuf[w] = v;
    __syncthreads();
    int nw = blockDim.x >> 5;
    v = (threadIdx.x < nw) ? sbuf[threadIdx.x] : 0.f;
    if (w == 0) {
        #pragma unroll
        for (int o = 16; o > 0; o >>= 1) v += __shfl_down_sync(0xffffffffu, v, o);
    }
    return v;  // valid on tid 0
}

__device__ __forceinline__ int blockReduceSumI(int v, int* sbuf) {
    __syncthreads();
    #pragma unroll
    for (int o = 16; o > 0; o >>= 1) v += __shfl_down_sync(0xffffffffu, v, o);
    int lane = threadIdx.x & 31, w = threadIdx.x >> 5;
    if (lane == 0) sbuf[w] = v;
    __syncthreads();
    int nw = blockDim.x >> 5;
    v = (threadIdx.x < nw) ? sbuf[threadIdx.x] : 0;
    if (w == 0) {
        #pragma unroll
        for (int o = 16; o > 0; o >>= 1) v += __shfl_down_sync(0xffffffffu, v, o);
    }
    return v;
}

// ---------------- kernel 0: init ----------------
__global__ void k_init() {
    int i = blockIdx.x * blockDim.x + threadIdx.x;
    if (i < BB * OO) g_bestprior[i] = 0xFFFFFFFFull;  // ratio=0, prior=0 (stored ~p)
    if (i < BB) g_numpos[i] = 0;
    if (i < 4) g_accum[i] = 0.f;
    if (i == 4) g_N = 0;
}

// ---------------- kernel 1: IOU matching (R12 proven version, verbatim) ----------------
// Per prior: argmax over truths via division-free cross-multiplication.
//   Single clamp: inter = w*max(h,0). If w<0 the pair's ratio is <=0; ordering by
//   cross-mult stays valid (bd,den>0). A negative best only happens when ALL truths
//   have empty overlap, in which case the prior is negative and bt is never used.
// Per truth: best prior via shared-gated exact division + packed 64-bit atomicMax.
__global__ void __launch_bounds__(MT) k_match(const float4* __restrict__ priors4,
                                              const float* __restrict__ targets) {
    const int b = blockIdx.y;
    __shared__ float4 s_t[OO];
    __shared__ float s_a[OO];
    __shared__ unsigned int s_gate[OO];
    __shared__ unsigned char s_lab[OO];
    const int tid = threadIdx.x;
    if (tid < OO) {
        const float* tp = targets + ((size_t)b * OO + tid) * 5;
        float4 t;
        t.x = tp[0]; t.y = tp[1]; t.z = tp[2]; t.w = tp[3];
        s_t[tid] = t;
        s_a[tid] = (t.z - t.x) * (t.w - t.y);
        s_gate[tid] = 0u;
        s_lab[tid] = (tp[4] >= 0.f) ? 1 : 0;
    }
    __syncthreads();

    const int pbase = blockIdx.x * (MT * MR) + tid;
    float px1[MR], py1[MR], px2[MR], py2[MR], ab[MR], bi[MR], bd[MR];
    int bt[MR];
    #pragma unroll
    for (int r = 0; r < MR; r++) {
        const float4 pr = priors4[pbase + r * MT];
        px1[r] = pr.x - pr.z * 0.5f; py1[r] = pr.y - pr.w * 0.5f;
        px2[r] = pr.x + pr.z * 0.5f; py2[r] = pr.y + pr.w * 0.5f;
        ab[r] = (px2[r] - px1[r]) * (py2[r] - py1[r]);
        bi[r] = -1.0f; bd[r] = 1.0f; bt[r] = 0;
    }

    #pragma unroll 2
    for (int t = 0; t < OO; t++) {
        const float4 tb = s_t[t];
        const float at = s_a[t];
        float rg = __uint_as_float(s_gate[t]);  // snapshot; atomics authoritative
        #pragma unroll
        for (int r = 0; r < MR; r++) {
            const float w = fminf(tb.z, px2[r]) - fmaxf(tb.x, px1[r]);
            const float h = fminf(tb.w, py2[r]) - fmaxf(tb.y, py1[r]);
            const float inter = w * fmaxf(h, 0.f);
            const float den = (at + ab[r]) - inter;
            if (inter * bd[r] > bi[r] * den) { bi[r] = inter; bd[r] = den; bt[r] = t; }
            if (inter > rg * den) {  // rare path
                const float ratio = inter / den;
                const unsigned int rb2 = __float_as_uint(ratio);
                const unsigned int old = atomicMax(&s_gate[t], rb2);
                if (rb2 > old) {
                    const unsigned long long pk =
                        ((unsigned long long)rb2 << 32) | (unsigned int)(~(pbase + r * MT));
                    atomicMax(&g_bestprior[b * OO + t], pk);
                }
                rg = __uint_as_float(rb2 > old ? rb2 : old);
            }
        }
    }

    #pragma unroll
    for (int r = 0; r < MR; r++) {
        const int conf = (bi[r] >= 0.5f * bd[r]) ? (int)s_lab[bt[r]] : 0;
        g_conf[(size_t)b * PP + pbase + r * MT] =
            (unsigned short)(conf | (bt[r] << 8));
    }
}

// ---------------- kernel 2: per-truth best-prior override ----------------
// Per batch b, ascending t by a single lane preserves last-write-wins on
// duplicate winning priors (matches jax .at[].set semantics).
__global__ void k_override(const float* __restrict__ targets) {
    const int b = blockIdx.x * blockDim.x + threadIdx.x;
    if (b >= BB) return;
    for (int t = 0; t < OO; t++) {
        const unsigned long long pk = g_bestprior[b * OO + t];
        const unsigned int p = ~(unsigned int)(pk & 0xFFFFFFFFu);
        const int lab = (targets[((size_t)b * OO + t) * 5 + 4] >= 0.f) ? 1 : 0;
        g_conf[(size_t)b * PP + p] = (unsigned short)(lab | (t << 8));  // ovl := 2 => pos
    }
}

// ---------------- kernel 3: per-prior loss terms (4 priors/thread, fused reduction) ----------------
__global__ void __launch_bounds__(256) k_loss(const float4* __restrict__ arm_loc4,
                                              const float4* __restrict__ arm_conf4,
                                              const float4* __restrict__ priors4,
                                              const float* __restrict__ targets) {
    __shared__ float sLL[8], sPLC[8];
    __shared__ int sNP[8];
    const int b = blockIdx.y;
    const int tid = threadIdx.x;
    const int p0 = (blockIdx.x * 256 + tid) * 4;      // 4 consecutive priors
    const size_t off0 = (size_t)b * PP + p0;

    const ushort4 ct4 = *reinterpret_cast<const ushort4*>(&g_conf[off0]);
    const float4 ca = arm_conf4[off0 >> 1];
    const float4 cb = arm_conf4[(off0 >> 1) + 1];

    unsigned short cts[4] = {ct4.x, ct4.y, ct4.z, ct4.w};
    float c0s[4] = {ca.x, ca.z, cb.x, cb.z};
    float c1s[4] = {ca.y, ca.w, cb.y, cb.w};

    float ll = 0.f, plc = 0.f;
    int np = 0;
    uint4 keys;
    unsigned int* kp = reinterpret_cast<unsigned int*>(&keys);

    #pragma unroll
    for (int j = 0; j < 4; j++) {
        const int conf = cts[j] & 0xFF;
        const int t = cts[j] >> 8;
        const bool pos = conf > 0;
        const float z = pos ? (c0s[j] - c1s[j]) : (c1s[j] - c0s[j]);
        const float lc = fmaxf(z, 0.f) + __logf(1.0f + __expf(-fabsf(z)));
        kp[j] = pos ? 0u : __float_as_uint(lc);
        if (pos) {
            np++; plc += lc;
            const float* tb = targets + ((size_t)b * OO + t) * 5;
            const float x1 = tb[0], y1 = tb[1], x2 = tb[2], y2 = tb[3];
            const float4 pr = priors4[p0 + j];
            const float gcx = ((x1 + x2) * 0.5f - pr.x) / (0.1f * pr.z);
            const float gcy = ((y1 + y2) * 0.5f - pr.y) / (0.1f * pr.w);
            const float gw = logf((x2 - x1) / pr.z) / 0.2f;
            const float gh = logf((y2 - y1) / pr.w) / 0.2f;
            const float4 al = arm_loc4[off0 + j];
            const float d0 = al.x - gcx, d1 = al.y - gcy, d2 = al.z - gw, d3 = al.w - gh;
            #define SL1(d) (fabsf(d) < 1.f ? 0.5f * (d) * (d) : fabsf(d) - 0.5f)
            ll += SL1(d0) + SL1(d1) + SL1(d2) + SL1(d3);
            #undef SL1
        }
    }
    *reinterpret_cast<uint4*>(&g_keys[off0]) = keys;

    // fused 3-way block reduction: one __syncthreads total
    #pragma unroll
    for (int o = 16; o > 0; o >>= 1) {
        ll  += __shfl_down_sync(0xffffffffu, ll, o);
        plc += __shfl_down_sync(0xffffffffu, plc, o);
        np  += __shfl_down_sync(0xffffffffu, np, o);
    }
    const int lane = tid & 31, w = tid >> 5;
    if (lane == 0) { sLL[w] = ll; sPLC[w] = plc; sNP[w] = np; }
    __syncthreads();
    if (w == 0) {
        float a = (lane < 8) ? sLL[lane] : 0.f;
        float c = (lane < 8) ? sPLC[lane] : 0.f;
        int   n = (lane < 8) ? sNP[lane] : 0;
        #pragma unroll
        for (int o = 4; o > 0; o >>= 1) {
            a += __shfl_down_sync(0xffffffffu, a, o);
            c += __shfl_down_sync(0xffffffffu, c, o);
            n += __shfl_down_sync(0xffffffffu, n, o);
        }
        if (lane == 0) {
            if (a != 0.f) atomicAdd(&g_accum[0], a);
            if (c != 0.f) atomicAdd(&g_accum[1], c);
            if (n != 0) { atomicAdd(&g_numpos[b], n); atomicAdd(&g_N, n); }
        }
    }
}

// ---------------- kernel 4: per-batch top-K sum via radix select (parallel scan) ----------------
__global__ void k_select() {
    extern __shared__ unsigned int s_keys[];  // PP uint32 = 128KB
    __shared__ int hist[256];
    __shared__ int ssum[256];   // inclusive suffix sums, indexed by tid (= 255 - digit)
    __shared__ int s_wsum[8];
    __shared__ int s_sel, s_rem;
    __shared__ float sbufF[32];
    __shared__ int sbufI[32];
    const int b = blockIdx.x;
    const int tid = threadIdx.x;  // 1024

    const int np = g_numpos[b];
    int K = 3 * np;
    if (K > PP - 1) K = PP - 1;
    if (K <= 0) return;  // uniform across block

    for (int i = tid; i < PP / 4; i += 1024)
        reinterpret_cast<uint4*>(s_keys)[i] =
            reinterpret_cast<const uint4*>(&g_keys[(size_t)b * PP])[i];
    __syncthreads();

    unsigned int prefix = 0, mask = 0;
    int remaining = K;
    for (int pass = 0; pass < 4; pass++) {
        const int shift = 24 - 8 * pass;
        if (tid < 256) hist[tid] = 0;
        __syncthreads();
        for (int i = tid; i < PP; i += 1024) {
            const unsigned int k = s_keys[i];
            if ((k & mask) == prefix) atomicAdd(&hist[(k >> shift) & 0xFFu], 1);
        }
        __syncthreads();

        // parallel suffix scan over 256 bins (tid -> digit 255-tid)
        int x = 0;
        if (tid < 256) {
            x = hist[255 - tid];
            #pragma unroll
            for (int o = 1; o < 32; o <<= 1) {
                const int y = __shfl_up_sync(0xffffffffu, x, o);
                if ((tid & 31) >= o) x += y;
            }
            if ((tid & 31) == 31) s_wsum[tid >> 5] = x;
        }
        __syncthreads();
        if (tid == 0) {
            int acc = 0;
            #pragma unroll
            for (int i = 0; i < 8; i++) { const int v = s_wsum[i]; s_wsum[i] = acc; acc += v; }
        }
        __syncthreads();
        int incl = 0;
        if (tid < 256) {
            incl = x + s_wsum[tid >> 5];
            ssum[tid] = incl;
        }
        __syncthreads();
        if (tid < 256) {
            const int above = tid ? ssum[tid - 1] : 0;  // count strictly above this digit
            if (incl >= remaining && above < remaining) {
                s_sel = 255 - tid;
                s_rem = remaining - above;
            }
        }
        __syncthreads();
        prefix |= ((unsigned int)s_sel) << shift;
        mask |= 0xFFu << shift;
        remaining = s_rem;
        __syncthreads();
    }

    const float kth = __uint_as_float(prefix);
    float sum = 0.f;
    int cnt = 0;
    for (int i = tid; i < PP; i += 1024) {
        const unsigned int k = s_keys[i];
        if (k > prefix) { sum += __uint_as_float(k); cnt++; }
    }
    const float sumT = blockReduceSumF(sum, sbufF);
    const int cntT = blockReduceSumI(cnt, sbufI);
    if (tid == 0) {
        const float total = sumT + (float)(K - cntT) * kth;
        atomicAdd(&g_accum[2], total);
    }
}

// ---------------- kernel 5: final combine ----------------
__global__ void k_final(float* __restrict__ out) {
    if (threadIdx.x == 0) {
        const float fN = (float)g_N;
        out[0] = g_accum[0] / fN;
        out[1] = (g_accum[1] + g_accum[2]) / fN;
    }
}

// ---------------- launch ----------------
extern "C" void kernel_launch(void* const* d_in, const int* in_sizes, int n_in,
                              void* d_out, int out_size) {
    const float* arm_loc  = (const float*)d_in[0];
    const float* arm_conf = (const float*)d_in[1];
    // d_in[2], d_in[3]: odm_loc / odm_conf unused by the reference loss
    const float* priors   = (const float*)d_in[4];
    const float* targets  = (const float*)d_in[5];
    float* out = (float*)d_out;

    cudaFuncSetAttribute(k_select, cudaFuncAttributeMaxDynamicSharedMemorySize, PP * 4);

    k_init<<<(BB * OO + 255) / 256, 256>>>();
    dim3 g1(PP / (MT * MR), BB);
    k_match<<<g1, MT>>>(reinterpret_cast<const float4*>(priors), targets);
    k_override<<<1, BB>>>(targets);
    dim3 g3(PP / (256 * 4), BB);
    k_loss<<<g3, 256>>>(reinterpret_cast<const float4*>(arm_loc),
                        reinterpret_cast<const float4*>(arm_conf),
                        reinterpret_cast<const float4*>(priors), targets);
    k_select<<<BB, 1024, PP * 4>>>();
    k_final<<<1, 32>>>(out);
}

// round 16
// speedup vs baseline: 2.1028x; 1.0438x over previous
#include <cuda_runtime.h>
#include <cstdint>

#define BB 64
#define PP 32768
#define OO 50

#define MT 512   // k_match threads per block (256->512: halves per-block gate warmup)
#define MR 4     // priors per thread in k_match

// ---------------- scratch (device globals; no allocations allowed) ----------------
__device__ unsigned long long g_bestprior[BB * OO];  // (ratio_bits<<32)|~prior
__device__ unsigned short g_conf[(size_t)BB * PP];   // conf_t (low 8) | tidx << 8
__device__ unsigned int g_keys[(size_t)BB * PP];     // lc bits for mining (pos -> 0)
__device__ int g_numpos[BB];
__device__ float g_accum[4];  // 0: loss_l, 1: pos lc sum, 2: mined neg lc sum
__device__ int g_N;
__device__ int g_ticket;
__device__ float* g_outp;  // stashed by a tiny kernel before k_select

// ---------------- helpers ----------------
__device__ __forceinline__ float blockReduceSumF(float v, float* sbuf) {
    __syncthreads();
    #pragma unroll
    for (int o = 16; o > 0; o >>= 1) v += __shfl_down_sync(0xffffffffu, v, o);
    int lane = threadIdx.x & 31, w = threadIdx.x >> 5;
    if (lane == 0) sbuf[w] = v;
    __syncthreads();
    int nw = blockDim.x >> 5;
    v = (threadIdx.x < nw) ? sbuf[threadIdx.x] : 0.f;
    if (w == 0) {
        #pragma unroll
        for (int o = 16; o > 0; o >>= 1) v += __shfl_down_sync(0xffffffffu, v, o);
    }
    return v;  // valid on tid 0
}

__device__ __forceinline__ int blockReduceSumI(int v, int* sbuf) {
    __syncthreads();
    #pragma unroll
    for (int o = 16; o > 0; o >>= 1) v += __shfl_down_sync(0xffffffffu, v, o);
    int lane = threadIdx.x & 31, w = threadIdx.x >> 5;
    if (lane == 0) sbuf[w] = v;
    __syncthreads();
    int nw = blockDim.x >> 5;
    v = (threadIdx.x < nw) ? sbuf[threadIdx.x] : 0;
    if (w == 0) {
        #pragma unroll
        for (int o = 16; o > 0; o >>= 1) v += __shfl_down_sync(0xffffffffu, v, o);
    }
    return v;
}

// ---------------- kernel 0: init ----------------
__global__ void k_init(float* out) {
    int i = blockIdx.x * blockDim.x + threadIdx.x;
    if (i < BB * OO) g_bestprior[i] = 0xFFFFFFFFull;  // ratio=0, prior=0 (stored ~p)
    if (i < BB) g_numpos[i] = 0;
    if (i < 4) g_accum[i] = 0.f;
    if (i == 4) { g_N = 0; g_ticket = 0; g_outp = out; }
}

// ---------------- kernel 1: IOU matching (R12 proven structure) ----------------
// Per prior: argmax over truths via division-free cross-multiplication.
//   Single clamp: inter = w*max(h,0). If w<0 the pair's ratio is <=0; ordering by
//   cross-mult stays valid (bd,den>0). A negative best only happens when ALL truths
//   have empty overlap, in which case the prior is negative and bt is never used.
// Per truth: best prior via shared-gated exact division + packed 64-bit atomicMax.
__global__ void __launch_bounds__(MT) k_match(const float4* __restrict__ priors4,
                                              const float* __restrict__ targets) {
    const int b = blockIdx.y;
    __shared__ float4 s_t[OO];
    __shared__ float s_a[OO];
    __shared__ unsigned int s_gate[OO];
    __shared__ unsigned char s_lab[OO];
    const int tid = threadIdx.x;
    if (tid < OO) {
        const float* tp = targets + ((size_t)b * OO + tid) * 5;
        float4 t;
        t.x = tp[0]; t.y = tp[1]; t.z = tp[2]; t.w = tp[3];
        s_t[tid] = t;
        s_a[tid] = (t.z - t.x) * (t.w - t.y);
        s_gate[tid] = 0u;
        s_lab[tid] = (tp[4] >= 0.f) ? 1 : 0;
    }
    __syncthreads();

    const int pbase = blockIdx.x * (MT * MR) + tid;
    float px1[MR], py1[MR], px2[MR], py2[MR], ab[MR], bi[MR], bd[MR];
    int bt[MR];
    #pragma unroll
    for (int r = 0; r < MR; r++) {
        const float4 pr = priors4[pbase + r * MT];
        px1[r] = pr.x - pr.z * 0.5f; py1[r] = pr.y - pr.w * 0.5f;
        px2[r] = pr.x + pr.z * 0.5f; py2[r] = pr.y + pr.w * 0.5f;
        ab[r] = (px2[r] - px1[r]) * (py2[r] - py1[r]);
        bi[r] = -1.0f; bd[r] = 1.0f; bt[r] = 0;
    }

    #pragma unroll 2
    for (int t = 0; t < OO; t++) {
        const float4 tb = s_t[t];
        const float at = s_a[t];
        float rg = __uint_as_float(s_gate[t]);  // snapshot; atomics authoritative
        #pragma unroll
        for (int r = 0; r < MR; r++) {
            const float w = fminf(tb.z, px2[r]) - fmaxf(tb.x, px1[r]);
            const float h = fminf(tb.w, py2[r]) - fmaxf(tb.y, py1[r]);
            const float inter = w * fmaxf(h, 0.f);
            const float den = (at + ab[r]) - inter;
            if (inter * bd[r] > bi[r] * den) { bi[r] = inter; bd[r] = den; bt[r] = t; }
            if (inter > rg * den) {  // rare path
                const float ratio = inter / den;
                const unsigned int rb2 = __float_as_uint(ratio);
                const unsigned int old = atomicMax(&s_gate[t], rb2);
                if (rb2 > old) {
                    const unsigned long long pk =
                        ((unsigned long long)rb2 << 32) | (unsigned int)(~(pbase + r * MT));
                    atomicMax(&g_bestprior[b * OO + t], pk);
                }
                rg = __uint_as_float(rb2 > old ? rb2 : old);
            }
        }
    }

    #pragma unroll
    for (int r = 0; r < MR; r++) {
        const int conf = (bi[r] >= 0.5f * bd[r]) ? (int)s_lab[bt[r]] : 0;
        g_conf[(size_t)b * PP + pbase + r * MT] =
            (unsigned short)(conf | (bt[r] << 8));
    }
}

// ---------------- kernel 2: per-truth best-prior override ----------------
// Per batch b, ascending t by a single lane preserves last-write-wins on
// duplicate winning priors (matches jax .at[].set semantics).
__global__ void k_override(const float* __restrict__ targets) {
    const int b = blockIdx.x * blockDim.x + threadIdx.x;
    if (b >= BB) return;
    for (int t = 0; t < OO; t++) {
        const unsigned long long pk = g_bestprior[b * OO + t];
        const unsigned int p = ~(unsigned int)(pk & 0xFFFFFFFFu);
        const int lab = (targets[((size_t)b * OO + t) * 5 + 4] >= 0.f) ? 1 : 0;
        g_conf[(size_t)b * PP + p] = (unsigned short)(lab | (t << 8));  // ovl := 2 => pos
    }
}

// ---------------- kernel 3: per-prior loss terms (4 priors/thread, fused reduction) ----------------
__global__ void __launch_bounds__(256) k_loss(const float4* __restrict__ arm_loc4,
                                              const float4* __restrict__ arm_conf4,
                                              const float4* __restrict__ priors4,
                                              const float* __restrict__ targets) {
    __shared__ float sLL[8], sPLC[8];
    __shared__ int sNP[8];
    const int b = blockIdx.y;
    const int tid = threadIdx.x;
    const int p0 = (blockIdx.x * 256 + tid) * 4;      // 4 consecutive priors
    const size_t off0 = (size_t)b * PP + p0;

    const ushort4 ct4 = *reinterpret_cast<const ushort4*>(&g_conf[off0]);
    const float4 ca = arm_conf4[off0 >> 1];
    const float4 cb = arm_conf4[(off0 >> 1) + 1];

    unsigned short cts[4] = {ct4.x, ct4.y, ct4.z, ct4.w};
    float c0s[4] = {ca.x, ca.z, cb.x, cb.z};
    float c1s[4] = {ca.y, ca.w, cb.y, cb.w};

    float ll = 0.f, plc = 0.f;
    int np = 0;
    uint4 keys;
    unsigned int* kp = reinterpret_cast<unsigned int*>(&keys);

    #pragma unroll
    for (int j = 0; j < 4; j++) {
        const int conf = cts[j] & 0xFF;
        const int t = cts[j] >> 8;
        const bool pos = conf > 0;
        const float z = pos ? (c0s[j] - c1s[j]) : (c1s[j] - c0s[j]);
        const float lc = fmaxf(z, 0.f) + __logf(1.0f + __expf(-fabsf(z)));
        kp[j] = pos ? 0u : __float_as_uint(lc);
        if (pos) {
            np++; plc += lc;
            const float* tb = targets + ((size_t)b * OO + t) * 5;
            const float x1 = tb[0], y1 = tb[1], x2 = tb[2], y2 = tb[3];
            const float4 pr = priors4[p0 + j];
            const float gcx = ((x1 + x2) * 0.5f - pr.x) / (0.1f * pr.z);
            const float gcy = ((y1 + y2) * 0.5f - pr.y) / (0.1f * pr.w);
            const float gw = logf((x2 - x1) / pr.z) / 0.2f;
            const float gh = logf((y2 - y1) / pr.w) / 0.2f;
            const float4 al = arm_loc4[off0 + j];
            const float d0 = al.x - gcx, d1 = al.y - gcy, d2 = al.z - gw, d3 = al.w - gh;
            #define SL1(d) (fabsf(d) < 1.f ? 0.5f * (d) * (d) : fabsf(d) - 0.5f)
            ll += SL1(d0) + SL1(d1) + SL1(d2) + SL1(d3);
            #undef SL1
        }
    }
    *reinterpret_cast<uint4*>(&g_keys[off0]) = keys;

    // fused 3-way block reduction: one __syncthreads total
    #pragma unroll
    for (int o = 16; o > 0; o >>= 1) {
        ll  += __shfl_down_sync(0xffffffffu, ll, o);
        plc += __shfl_down_sync(0xffffffffu, plc, o);
        np  += __shfl_down_sync(0xffffffffu, np, o);
    }
    const int lane = tid & 31, w = tid >> 5;
    if (lane == 0) { sLL[w] = ll; sPLC[w] = plc; sNP[w] = np; }
    __syncthreads();
    if (w == 0) {
        float a = (lane < 8) ? sLL[lane] : 0.f;
        float c = (lane < 8) ? sPLC[lane] : 0.f;
        int   n = (lane < 8) ? sNP[lane] : 0;
        #pragma unroll
        for (int o = 4; o > 0; o >>= 1) {
            a += __shfl_down_sync(0xffffffffu, a, o);
            c += __shfl_down_sync(0xffffffffu, c, o);
            n += __shfl_down_sync(0xffffffffu, n, o);
        }
        if (lane == 0) {
            if (a != 0.f) atomicAdd(&g_accum[0], a);
            if (c != 0.f) atomicAdd(&g_accum[1], c);
            if (n != 0) { atomicAdd(&g_numpos[b], n); atomicAdd(&g_N, n); }
        }
    }
}

// ---------------- kernel 4: per-batch top-K sum via radix select + final combine ----------------
__global__ void k_select() {
    extern __shared__ unsigned int s_keys[];  // PP uint32 = 128KB
    __shared__ int hist[256];
    __shared__ int ssum[256];   // inclusive suffix sums, indexed by tid (= 255 - digit)
    __shared__ int s_wsum[8];
    __shared__ int s_sel, s_rem;
    __shared__ float sbufF[32];
    __shared__ int sbufI[32];
    const int b = blockIdx.x;
    const int tid = threadIdx.x;  // 1024

    const int np = g_numpos[b];
    int K = 3 * np;
    if (K > PP - 1) K = PP - 1;

    if (K > 0) {
        for (int i = tid; i < PP / 4; i += 1024)
            reinterpret_cast<uint4*>(s_keys)[i] =
                reinterpret_cast<const uint4*>(&g_keys[(size_t)b * PP])[i];
        __syncthreads();

        unsigned int prefix = 0, mask = 0;
        int remaining = K;
        for (int pass = 0; pass < 4; pass++) {
            const int shift = 24 - 8 * pass;
            if (tid < 256) hist[tid] = 0;
            __syncthreads();
            for (int i = tid; i < PP; i += 1024) {
                const unsigned int k = s_keys[i];
                if ((k & mask) == prefix) atomicAdd(&hist[(k >> shift) & 0xFFu], 1);
            }
            __syncthreads();

            // parallel suffix scan over 256 bins (tid -> digit 255-tid)
            int x = 0;
            if (tid < 256) {
                x = hist[255 - tid];
                #pragma unroll
                for (int o = 1; o < 32; o <<= 1) {
                    const int y = __shfl_up_sync(0xffffffffu, x, o);
                    if ((tid & 31) >= o) x += y;
                }
                if ((tid & 31) == 31) s_wsum[tid >> 5] = x;
            }
            __syncthreads();
            if (tid == 0) {
                int acc = 0;
                #pragma unroll
                for (int i = 0; i < 8; i++) { const int v = s_wsum[i]; s_wsum[i] = acc; acc += v; }
            }
            __syncthreads();
            int incl = 0;
            if (tid < 256) {
                incl = x + s_wsum[tid >> 5];
                ssum[tid] = incl;
            }
            __syncthreads();
            if (tid < 256) {
                const int above = tid ? ssum[tid - 1] : 0;  // count strictly above this digit
                if (incl >= remaining && above < remaining) {
                    s_sel = 255 - tid;
                    s_rem = remaining - above;
                }
            }
            __syncthreads();
            prefix |= ((unsigned int)s_sel) << shift;
            mask |= 0xFFu << shift;
            remaining = s_rem;
            __syncthreads();
        }

        const float kth = __uint_as_float(prefix);
        float sum = 0.f;
        int cnt = 0;
        for (int i = tid; i < PP; i += 1024) {
            const unsigned int k = s_keys[i];
            if (k > prefix) { sum += __uint_as_float(k); cnt++; }
        }
        const float sumT = blockReduceSumF(sum, sbufF);
        const int cntT = blockReduceSumI(cnt, sbufI);
        if (tid == 0) {
            const float total = sumT + (float)(K - cntT) * kth;
            atomicAdd(&g_accum[2], total);
        }
    }
    __syncthreads();

    // last block folds the final combine (saves one kernel launch)
    if (tid == 0) {
        __threadfence();
        const int done = atomicAdd(&g_ticket, 1);
        if (done == BB - 1) {
            __threadfence();
            const float fN = (float)g_N;
            float* out = g_outp;
            out[0] = g_accum[0] / fN;
            out[1] = (g_accum[1] + g_accum[2]) / fN;
        }
    }
}

// ---------------- launch ----------------
extern "C" void kernel_launch(void* const* d_in, const int* in_sizes, int n_in,
                              void* d_out, int out_size) {
    const float* arm_loc  = (const float*)d_in[0];
    const float* arm_conf = (const float*)d_in[1];
    // d_in[2], d_in[3]: odm_loc / odm_conf unused by the reference loss
    const float* priors   = (const float*)d_in[4];
    const float* targets  = (const float*)d_in[5];
    float* out = (float*)d_out;

    cudaFuncSetAttribute(k_select, cudaFuncAttributeMaxDynamicSharedMemorySize, PP * 4);

    k_init<<<(BB * OO + 255) / 256, 256>>>(out);
    dim3 g1(PP / (MT * MR), BB);
    k_match<<<g1, MT>>>(reinterpret_cast<const float4*>(priors), targets);
    k_override<<<1, BB>>>(targets);
    dim3 g3(PP / (256 * 4), BB);
    k_loss<<<g3, 256>>>(reinterpret_cast<const float4*>(arm_loc),
                        reinterpret_cast<const float4*>(arm_conf),
                        reinterpret_cast<const float4*>(priors), targets);
    k_select<<<BB, 1024, PP * 4>>>();
}